// round 15
// baseline (speedup 1.0000x reference)
#include <cuda_runtime.h>
#include <cstdint>

typedef unsigned long long ull;

// ---------------------------------------------------------------------------
// Scratch buffers (device globals; no allocation allowed)
// ---------------------------------------------------------------------------
__device__ float g_w1 [786432];    // [4,12,128,128]
__device__ float g_c1 [1048576];   // [4,16,128,128]
__device__ float g_w2 [1048576];   // [4,64,64,64]
__device__ float g_c2 [1048576];   // [4,64,64,64]
__device__ float g_w3 [1048576];   // [4,256,32,32]
__device__ float g_c3 [1048576];   // [4,256,32,32]
__device__ float g_w4 [1048576];   // [4,1024,16,16]
__device__ float g_c4 [1048576];
__device__ float g_c5 [1048576];
__device__ float g_iw4[2097152];   // [4,512,32,32]
__device__ float g_iw3[2097152];   // [4,128,64,64]
__device__ float g_iw2[2097152];   // [4,32,128,128]
__device__ float g_ic1[1048576];   // [4,16,128,128]
__device__ float g_iw1[786432];    // [4,12,128,128]
__device__ float g_part[4194304];  // 4 x 1M partial-sum buffers
__device__ float2 g_wpk[4718592];  // packed weights [IC*9][OC/2] (max: conv4)

// ---------------------------------------------------------------------------
// f32x2 packed helpers (Blackwell FFMA2)
// ---------------------------------------------------------------------------
__device__ __forceinline__ ull pk(float x, float y) {
    ull r;
    asm("mov.b64 %0, {%1, %2};" : "=l"(r) : "f"(x), "f"(y));
    return r;
}
__device__ __forceinline__ void upk(float& x, float& y, ull v) {
    asm("mov.b64 {%0, %1}, %2;" : "=f"(x), "=f"(y) : "l"(v));
}
__device__ __forceinline__ void fma2(ull& d, ull a, ull b) {
    asm("fma.rn.f32x2 %0, %1, %2, %0;" : "+l"(d) : "l"(a), "l"(b));
}

// ---------------------------------------------------------------------------
// Weight pre-pack: w[OC][IC][9] -> wpk[t9][ocpair] with t9 = ic*9+t.
// ---------------------------------------------------------------------------
__global__ void packw_k(const float* __restrict__ w, float2* __restrict__ wpk,
                        int OCp, int IC9) {
    int i = blockIdx.x * blockDim.x + threadIdx.x;
    int total = OCp * IC9;
    if (i >= total) return;
    int p  = i / IC9;
    int t9 = i - p * IC9;
    float a = w[(size_t)(2 * p) * IC9 + t9];
    float b = w[(size_t)(2 * p + 1) * IC9 + t9];
    wpk[(size_t)t9 * OCp + p] = make_float2(a, b);
}

// ---------------------------------------------------------------------------
// Haar DWT (standalone — only for the network input x)
// ---------------------------------------------------------------------------
__global__ void wt_k(const float* __restrict__ in, float* __restrict__ out,
                     int B, int C, int H, int W) {
    int Ho = H >> 1, Wo = W >> 1;
    int total = B * C * Ho * Wo;
    int i = blockIdx.x * blockDim.x + threadIdx.x;
    if (i >= total) return;
    int w = i % Wo;
    int h = (i / Wo) % Ho;
    int c = (i / (Wo * Ho)) % C;
    int b = i / (Wo * Ho * C);
    const float* p = in + ((size_t)(b * C + c) * H + 2 * h) * W + 2 * w;
    float a  = p[0], bb = p[1], cc = p[W], d = p[W + 1];
    float ll = 0.25f * (a + bb + cc + d);
    float hl = 0.5f  * (a + bb - cc - d);
    float lh = 0.5f  * (a - bb + cc - d);
    float hh = 0.5f  * (a - bb - cc + d);
    size_t ob = ((size_t)(b * 4 * C + 4 * c) * Ho + h) * Wo + w;
    size_t cs = (size_t)Ho * Wo;
    out[ob]          = ll;
    out[ob + cs]     = (hl + 1.f) * 0.5f;
    out[ob + 2 * cs] = (lh + 1.f) * 0.5f;
    out[ob + 3 * cs] = (hh + 1.f) * 0.5f;
}

// ---------------------------------------------------------------------------
// Partial direct 3x3 conv, pad=1 — oc-pair lane packing, 2x2 px per thread.
// Pre-packed weights streamed straight into smem. NP oc-pairs per thread,
// explicit per-thread input double-buffer. 64-thread blocks, 12 blocks/SM.
// ---------------------------------------------------------------------------
template <int H, int W, int TPX, int NP, int ICCHUNK>
__global__ void __launch_bounds__(TPX, 12)
convpart_k(const float* __restrict__ in, const float2* __restrict__ wpk,
           float* __restrict__ part, int IC, int OC, int ics) {
    constexpr int NT = TPX;
    constexpr int DN = ICCHUNK * 9 * NP;
    constexpr int TILESIMG = (H / 2) * (W / 2);

    __shared__ __align__(16) float2 s_pk[2][DN];

    const int tid = threadIdx.x;
    const int g   = blockIdx.x * TPX + tid;
    const int img = g / TILESIMG;
    const int rem = g % TILESIMG;
    const int h0  = (rem / (W / 2)) * 2;
    const int w0  = (rem % (W / 2)) * 2;
    const int ocp0 = blockIdx.y * NP;
    const int OCp  = OC >> 1;
    const int z   = blockIdx.z;
    const int ic0 = z * ics;

    const size_t HW = (size_t)H * W;
    const bool vr0 = (h0 > 0);
    const bool vr3 = (h0 + 2 < H);
    const bool lok = (w0 > 0);
    const bool rok = (w0 + 2 < W);

    ull acc[NP][2][2];
#pragma unroll
    for (int np = 0; np < NP; np++)
#pragma unroll
        for (int r = 0; r < 2; r++)
#pragma unroll
            for (int c = 0; c < 2; c++) acc[np][r][c] = pk(0.f, 0.f);

    const float* p0 = in + ((size_t)img * IC + ic0) * HW + (size_t)(h0 - 1) * W + (w0 - 1);
    const int nch = ics / ICCHUNK;

    auto load_chunk = [&](int c, int buf) {
        const float2* srcbase = wpk + ((size_t)(ic0 + c * ICCHUNK) * 9) * OCp + ocp0;
        if constexpr ((NP % 2) == 0) {
            for (int i = tid; i < DN / 2; i += NT) {
                int r = i / (NP / 2);
                int q = (i - r * (NP / 2)) * 2;
                const float2* src = srcbase + (size_t)r * OCp + q;
                uint32_t dst = (uint32_t)__cvta_generic_to_shared(&s_pk[buf][r * NP + q]);
                asm volatile("cp.async.ca.shared.global [%0], [%1], 16;" :: "r"(dst), "l"(src));
            }
        } else {
            for (int i = tid; i < DN; i += NT) {
                int r = i / NP;
                int q = i - r * NP;
                const float2* src = srcbase + (size_t)r * OCp + q;
                uint32_t dst = (uint32_t)__cvta_generic_to_shared(&s_pk[buf][r * NP + q]);
                asm volatile("cp.async.ca.shared.global [%0], [%1], 8;" :: "r"(dst), "l"(src));
            }
        }
    };

    load_chunk(0, 0);
    asm volatile("cp.async.commit_group;" ::: "memory");

    float cl[2][4], cx[2][4], cy[2][4], cr[2][4];

    for (int ch = 0; ch < nch; ch++) {
        asm volatile("cp.async.wait_group 0;" ::: "memory");
        __syncthreads();
        if (ch + 1 < nch) load_chunk(ch + 1, (ch + 1) & 1);
        asm volatile("cp.async.commit_group;" ::: "memory");

        const float2* wchunk = s_pk[ch & 1];
        const float* pb = p0 + (size_t)(ch * ICCHUNK) * HW;
#pragma unroll
        for (int ri = 0; ri < 4; ri++) {
            bool vr = (ri == 0) ? vr0 : (ri == 3) ? vr3 : true;
            const float* q = pb + ri * W;
            float2 m = make_float2(0.f, 0.f);
            float l = 0.f, r = 0.f;
            if (vr) {
                m = *(const float2*)(q + 1);
                if (lok) l = q[0];
                if (rok) r = q[3];
            }
            cl[0][ri] = l; cx[0][ri] = m.x; cy[0][ri] = m.y; cr[0][ri] = r;
        }

#pragma unroll 2
        for (int kk = 0; kk < ICCHUNK; kk++) {
            const int cb = kk & 1;
            if (kk + 1 < ICCHUNK) {
                const float* pn = pb + (size_t)(kk + 1) * HW;
#pragma unroll
                for (int ri = 0; ri < 4; ri++) {
                    bool vr = (ri == 0) ? vr0 : (ri == 3) ? vr3 : true;
                    const float* q = pn + ri * W;
                    float2 m = make_float2(0.f, 0.f);
                    float l = 0.f, r = 0.f;
                    if (vr) {
                        m = *(const float2*)(q + 1);
                        if (lok) l = q[0];
                        if (rok) r = q[3];
                    }
                    cl[cb ^ 1][ri] = l; cx[cb ^ 1][ri] = m.x;
                    cy[cb ^ 1][ri] = m.y; cr[cb ^ 1][ri] = r;
                }
            }
            ull bp[4][4];
#pragma unroll
            for (int ri = 0; ri < 4; ri++) {
                bp[ri][0] = pk(cl[cb][ri], cl[cb][ri]);
                bp[ri][1] = pk(cx[cb][ri], cx[cb][ri]);
                bp[ri][2] = pk(cy[cb][ri], cy[cb][ri]);
                bp[ri][3] = pk(cr[cb][ri], cr[cb][ri]);
            }
            const float2* wrow = wchunk + kk * 9 * NP;
#pragma unroll
            for (int ki = 0; ki < 3; ki++)
#pragma unroll
                for (int kj = 0; kj < 3; kj++) {
                    const int t = ki * 3 + kj;
                    ull wv[NP];
                    if constexpr ((NP % 2) == 0) {
#pragma unroll
                        for (int q2 = 0; q2 < NP / 2; q2++) {
                            ulonglong2 u = *(const ulonglong2*)&wrow[t * NP + 2 * q2];
                            wv[2 * q2]     = u.x;
                            wv[2 * q2 + 1] = u.y;
                        }
                    } else {
#pragma unroll
                        for (int np = 0; np < NP; np++)
                            wv[np] = *(const ull*)&wrow[t * NP + np];
                    }
#pragma unroll
                    for (int np = 0; np < NP; np++) {
                        fma2(acc[np][0][0], bp[ki][kj],         wv[np]);
                        fma2(acc[np][0][1], bp[ki][kj + 1],     wv[np]);
                        fma2(acc[np][1][0], bp[ki + 1][kj],     wv[np]);
                        fma2(acc[np][1][1], bp[ki + 1][kj + 1], wv[np]);
                    }
                }
        }
    }

    float* pout = part + (size_t)z * 4 * OC * HW;
#pragma unroll
    for (int np = 0; np < NP; np++) {
        float a00, b00, a01, b01, a10, b10, a11, b11;
        upk(a00, b00, acc[np][0][0]); upk(a01, b01, acc[np][0][1]);
        upk(a10, b10, acc[np][1][0]); upk(a11, b11, acc[np][1][1]);
        const int ocA = 2 * (ocp0 + np);
        size_t baseA = ((size_t)(img * OC + ocA) * H + h0) * W + w0;
        size_t baseB = baseA + HW;
        *(float2*)&pout[baseA]     = make_float2(a00, a01);
        *(float2*)&pout[baseA + W] = make_float2(a10, a11);
        *(float2*)&pout[baseB]     = make_float2(b00, b01);
        *(float2*)&pout[baseB + W] = make_float2(b10, b11);
    }
}

// ---------------------------------------------------------------------------
// Combine four partial buffers: out = act(p0+p1+p2+p3 + bias (+skip))
// ---------------------------------------------------------------------------
template <bool RELU, bool ADD>
__global__ void combine4_k(const float* __restrict__ part, const float* __restrict__ bias,
                           const float* __restrict__ addsrc, float* __restrict__ out,
                           int OC, int HW, int total) {
    int i = (blockIdx.x * blockDim.x + threadIdx.x) * 2;
    if (i >= total) return;
    int c = (i / HW) % OC;
    float2 p0 = *(const float2*)&part[i];
    float2 p1 = *(const float2*)&part[total + i];
    float2 p2 = *(const float2*)&part[2 * (size_t)total + i];
    float2 p3 = *(const float2*)&part[3 * (size_t)total + i];
    float bv = bias[c];
    float v0 = (p0.x + p1.x) + (p2.x + p3.x) + bv;
    float v1 = (p0.y + p1.y) + (p2.y + p3.y) + bv;
    if (ADD) {
        float2 s = *(const float2*)&addsrc[i];
        v0 += s.x; v1 += s.y;
    }
    if (RELU) {
        v0 = (v0 >= 0.f) ? v0 : 0.2f * v0;
        v1 = (v1 >= 0.f) ? v1 : 0.2f * v1;
    }
    *(float2*)&out[i] = make_float2(v0, v1);
}

// ---------------------------------------------------------------------------
// Combine four partials + lrelu + fused Haar DWT of the result.
// ---------------------------------------------------------------------------
__global__ void combine4wt_k(const float* __restrict__ part, const float* __restrict__ bias,
                             float* __restrict__ out, float* __restrict__ wtout,
                             int OC, int H, int W, int total) {
    int HW = H * W;
    int nblk = total / 4;
    int i = blockIdx.x * blockDim.x + threadIdx.x;
    if (i >= nblk) return;
    int Wh = W / 2;
    int w2 = i % Wh;
    int h2 = (i / Wh) % (H / 2);
    int bc = i / (HW / 4);
    size_t base = (size_t)bc * HW + (size_t)(2 * h2) * W + 2 * w2;
    float bv = bias[bc % OC];
    float v00 = bv, v01 = bv, v10 = bv, v11 = bv;
#pragma unroll
    for (int z = 0; z < 4; z++) {
        const float* p = part + (size_t)z * total;
        float2 a = *(const float2*)&p[base];
        float2 b = *(const float2*)&p[base + W];
        v00 += a.x; v01 += a.y; v10 += b.x; v11 += b.y;
    }
    v00 = (v00 >= 0.f) ? v00 : 0.2f * v00;
    v01 = (v01 >= 0.f) ? v01 : 0.2f * v01;
    v10 = (v10 >= 0.f) ? v10 : 0.2f * v10;
    v11 = (v11 >= 0.f) ? v11 : 0.2f * v11;
    *(float2*)&out[base]     = make_float2(v00, v01);
    *(float2*)&out[base + W] = make_float2(v10, v11);

    float ll = 0.25f * (v00 + v01 + v10 + v11);
    float hl = 0.5f  * (v00 + v01 - v10 - v11);
    float lh = 0.5f  * (v00 - v01 + v10 - v11);
    float hh = 0.5f  * (v00 - v01 - v10 + v11);
    hl = (hl + 1.f) * 0.5f; lh = (lh + 1.f) * 0.5f; hh = (hh + 1.f) * 0.5f;
    int c = bc % OC, b_ = bc / OC;
    size_t cs = (size_t)HW / 4;
    size_t ob = ((size_t)(b_ * 4 * OC + 4 * c)) * cs + (size_t)h2 * Wh + w2;
    wtout[ob]          = ll;
    wtout[ob + cs]     = hl;
    wtout[ob + 2 * cs] = lh;
    wtout[ob + 3 * cs] = hh;
}

// ---------------------------------------------------------------------------
// Fused: combine four partials (+ optional skip-add) + lrelu + IWT + concat.
// Thread handles one base channel c, 2 band-space pixels -> 2x4 output px.
// Also copies the skip channels into out[:, :Csrc] (separate index range).
// ---------------------------------------------------------------------------
template <bool ADD>
__global__ void comb4iwtcat_k(const float* __restrict__ part, const float* __restrict__ bias,
                              const float* __restrict__ addsrc, const float* __restrict__ skip,
                              float* __restrict__ out,
                              int B, int C4, int H, int W, int Ctot, int total) {
    int C = C4 >> 2;
    int Csrc = Ctot - C;
    int Wh = W / 2;
    int Niwt = B * C * H * Wh;
    int HWo = 4 * H * W;
    int npc = HWo / 2;
    int Ncopy2 = B * Csrc * npc;
    int i = blockIdx.x * blockDim.x + threadIdx.x;
    if (i < Niwt) {
        int w0 = (i % Wh) * 2;
        int h  = (i / Wh) % H;
        int c  = (i / (Wh * H)) % C;
        int b  = i / (Wh * H * C);
        float2 v[4];
#pragma unroll
        for (int k = 0; k < 4; k++) {
            size_t base = ((size_t)(b * C4 + 4 * c + k) * H + h) * W + w0;
            float2 s0 = *(const float2*)&part[base];
            float2 s1 = *(const float2*)&part[(size_t)total + base];
            float2 s2 = *(const float2*)&part[2 * (size_t)total + base];
            float2 s3 = *(const float2*)&part[3 * (size_t)total + base];
            float bv = bias[4 * c + k];
            float x = (s0.x + s1.x) + (s2.x + s3.x) + bv;
            float y = (s0.y + s1.y) + (s2.y + s3.y) + bv;
            if (ADD) {
                float2 a = *(const float2*)&addsrc[base];
                x += a.x; y += a.y;
            }
            x = (x >= 0.f) ? x : 0.2f * x;
            y = (y >= 0.f) ? y : 0.2f * y;
            if (k) { x = 2.f * x - 1.f; y = 2.f * y - 1.f; }
            v[k] = make_float2(x, y);
        }
        float x00a = v[0].x + 0.5f * ( v[1].x + v[2].x + v[3].x);
        float x01a = v[0].x + 0.5f * ( v[1].x - v[2].x - v[3].x);
        float x10a = v[0].x + 0.5f * (-v[1].x + v[2].x - v[3].x);
        float x11a = v[0].x + 0.5f * (-v[1].x - v[2].x + v[3].x);
        float x00b = v[0].y + 0.5f * ( v[1].y + v[2].y + v[3].y);
        float x01b = v[0].y + 0.5f * ( v[1].y - v[2].y - v[3].y);
        float x10b = v[0].y + 0.5f * (-v[1].y + v[2].y - v[3].y);
        float x11b = v[0].y + 0.5f * (-v[1].y - v[2].y + v[3].y);
        int W2 = 2 * W;
        size_t ob = ((size_t)(b * Ctot + Csrc + c) * 2 * H + 2 * h) * W2 + 2 * w0;
        *(float4*)&out[ob]      = make_float4(x00a, x01a, x00b, x01b);
        *(float4*)&out[ob + W2] = make_float4(x10a, x11a, x10b, x11b);
    } else {
        int j = i - Niwt;
        if (j >= Ncopy2) return;
        int pos = j % npc;
        int c   = (j / npc) % Csrc;
        int b   = j / (npc * Csrc);
        *(float2*)&out[((size_t)(b * Ctot) + c) * HWo + 2 * pos] =
            *(const float2*)&skip[((size_t)(b * Csrc) + c) * HWo + 2 * pos];
    }
}

// ---------------------------------------------------------------------------
// Final: y = iwt(iw1[4,12,128,128]); out = 1x1 conv cfin @ y -> [4,3,256,256]
// ---------------------------------------------------------------------------
__global__ void final_k(const float* __restrict__ in, const float* __restrict__ cfin,
                        float* __restrict__ out, int B) {
    const int H = 128, W = 128;
    int total = B * H * W;
    int i = blockIdx.x * blockDim.x + threadIdx.x;
    if (i >= total) return;
    int w = i % W;
    int h = (i / W) % H;
    int b = i / (W * H);

    float y00[3], y01[3], y10[3], y11[3];
#pragma unroll
    for (int c = 0; c < 3; c++) {
        size_t ib = ((size_t)(b * 12 + 4 * c) * H + h) * W + w;
        size_t cs = (size_t)H * W;
        float v0 = in[ib];
        float v1 = 2.f * in[ib + cs]     - 1.f;
        float v2 = 2.f * in[ib + 2 * cs] - 1.f;
        float v3 = 2.f * in[ib + 3 * cs] - 1.f;
        y00[c] = v0 + 0.5f * ( v1 + v2 + v3);
        y01[c] = v0 + 0.5f * ( v1 - v2 - v3);
        y10[c] = v0 + 0.5f * (-v1 + v2 - v3);
        y11[c] = v0 + 0.5f * (-v1 - v2 + v3);
    }
    float m[9];
#pragma unroll
    for (int j = 0; j < 9; j++) m[j] = cfin[j];

    const int HO = 256, WO = 256;
#pragma unroll
    for (int o = 0; o < 3; o++) {
        float o00 = m[o*3+0]*y00[0] + m[o*3+1]*y00[1] + m[o*3+2]*y00[2];
        float o01 = m[o*3+0]*y01[0] + m[o*3+1]*y01[1] + m[o*3+2]*y01[2];
        float o10 = m[o*3+0]*y10[0] + m[o*3+1]*y10[1] + m[o*3+2]*y10[2];
        float o11 = m[o*3+0]*y11[0] + m[o*3+1]*y11[1] + m[o*3+2]*y11[2];
        size_t ob = ((size_t)(b * 3 + o) * HO + 2 * h) * WO + 2 * w;
        out[ob]          = o00;
        out[ob + 1]      = o01;
        out[ob + WO]     = o10;
        out[ob + WO + 1] = o11;
    }
}

// ---------------------------------------------------------------------------
// Host side
// ---------------------------------------------------------------------------
static inline int ceil_div(int a, int b) { return (a + b - 1) / b; }

extern "C" void kernel_launch(void* const* d_in, const int* in_sizes, int n_in,
                              void* d_out, int out_size) {
    (void)in_sizes; (void)n_in; (void)out_size;
    const float* x        = (const float*)d_in[0];
    const float* conv1_w  = (const float*)d_in[1];
    const float* conv1_b  = (const float*)d_in[2];
    const float* conv2_w  = (const float*)d_in[3];
    const float* conv2_b  = (const float*)d_in[4];
    const float* conv3_w  = (const float*)d_in[5];
    const float* conv3_b  = (const float*)d_in[6];
    const float* conv4_w  = (const float*)d_in[7];
    const float* conv4_b  = (const float*)d_in[8];
    const float* convd4_w = (const float*)d_in[9];
    const float* convd4_b = (const float*)d_in[10];
    const float* convd3_w = (const float*)d_in[11];
    const float* convd3_b = (const float*)d_in[12];
    const float* convd2_w = (const float*)d_in[13];
    const float* convd2_b = (const float*)d_in[14];
    const float* convd1_w = (const float*)d_in[15];
    const float* convd1_b = (const float*)d_in[16];
    const float* cfin_w   = (const float*)d_in[17];
    float* out = (float*)d_out;

    static float *p_w1=nullptr,*p_c1,*p_w2,*p_c2,*p_w3,*p_c3,*p_w4,*p_c4,*p_c5,
                 *p_iw4,*p_iw3,*p_iw2,*p_ic1,*p_iw1,*p_part;
    static float2 *p_wpk;
    if (!p_w1) {
        cudaGetSymbolAddress((void**)&p_w1,  g_w1);
        cudaGetSymbolAddress((void**)&p_c1,  g_c1);
        cudaGetSymbolAddress((void**)&p_w2,  g_w2);
        cudaGetSymbolAddress((void**)&p_c2,  g_c2);
        cudaGetSymbolAddress((void**)&p_w3,  g_w3);
        cudaGetSymbolAddress((void**)&p_c3,  g_c3);
        cudaGetSymbolAddress((void**)&p_w4,  g_w4);
        cudaGetSymbolAddress((void**)&p_c4,  g_c4);
        cudaGetSymbolAddress((void**)&p_c5,  g_c5);
        cudaGetSymbolAddress((void**)&p_iw4, g_iw4);
        cudaGetSymbolAddress((void**)&p_iw3, g_iw3);
        cudaGetSymbolAddress((void**)&p_iw2, g_iw2);
        cudaGetSymbolAddress((void**)&p_ic1, g_ic1);
        cudaGetSymbolAddress((void**)&p_iw1, g_iw1);
        cudaGetSymbolAddress((void**)&p_part, g_part);
        cudaGetSymbolAddress((void**)&p_wpk, g_wpk);
    }

    auto packw = [&](const float* w, int OC, int IC) {
        int OCp = OC / 2, IC9 = IC * 9;
        packw_k<<<ceil_div(OCp * IC9, 256), 256>>>(w, p_wpk, OCp, IC9);
    };

    // w1 = wt(x)
    wt_k<<<ceil_div(4*3*128*128, 256), 256>>>(x, p_w1, 4, 3, 256, 256);

    // conv1: 12->16 @128². grid (256,2,4)=2048 x64
    packw(conv1_w, 16, 12);
    convpart_k<128,128,64,4,3><<<dim3(256, 2, 4), 64>>>(
        p_w1, p_wpk, p_part, 12, 16, 3);
    combine4wt_k<<<ceil_div(1048576/4, 256), 256>>>(
        p_part, conv1_b, p_c1, p_w2, 16, 128, 128, 1048576);

    // conv2: 64->64 @64². grid (64,8,4)=2048
    packw(conv2_w, 64, 64);
    convpart_k<64,64,64,4,16><<<dim3(64, 8, 4), 64>>>(
        p_w2, p_wpk, p_part, 64, 64, 16);
    combine4wt_k<<<ceil_div(1048576/4, 256), 256>>>(
        p_part, conv2_b, p_c2, p_w3, 64, 64, 64, 1048576);

    // conv3: 256->256 @32². grid (16,32,4)=2048
    packw(conv3_w, 256, 256);
    convpart_k<32,32,64,4,16><<<dim3(16, 32, 4), 64>>>(
        p_w3, p_wpk, p_part, 256, 256, 64);
    combine4wt_k<<<ceil_div(1048576/4, 256), 256>>>(
        p_part, conv3_b, p_c3, p_w4, 256, 32, 32, 1048576);

    // bottleneck: three conv4 1024->1024 @16². grid (4,128,4)=2048
    packw(conv4_w, 1024, 1024);
    convpart_k<16,16,64,4,16><<<dim3(4, 128, 4), 64>>>(
        p_w4, p_wpk, p_part, 1024, 1024, 256);
    combine4_k<true,false><<<ceil_div(1048576/2, 256), 256>>>(
        p_part, conv4_b, nullptr, p_c4, 1024, 16*16, 1048576);
    convpart_k<16,16,64,4,16><<<dim3(4, 128, 4), 64>>>(
        p_c4, p_wpk, p_part, 1024, 1024, 256);
    combine4_k<true,false><<<ceil_div(1048576/2, 256), 256>>>(
        p_part, conv4_b, nullptr, p_c5, 1024, 16*16, 1048576);
    convpart_k<16,16,64,4,16><<<dim3(4, 128, 4), 64>>>(
        p_c5, p_wpk, p_part, 1024, 1024, 256);
    // fused: combine + w4 skip-add + lrelu + IWT + concat with c3 -> iw4
    comb4iwtcat_k<true><<<ceil_div(4*256*16*8 + 4*256*512, 256), 256>>>(
        p_part, conv4_b, p_w4, p_c3, p_iw4, 4, 1024, 16, 16, 512, 1048576);

    // convd4: 512->256 @32². grid (16,32,4)=2048
    packw(convd4_w, 256, 512);
    convpart_k<32,32,64,4,16><<<dim3(16, 32, 4), 64>>>(
        p_iw4, p_wpk, p_part, 512, 256, 128);
    // fused: combine + lrelu + IWT + concat with c2 -> iw3
    comb4iwtcat_k<false><<<ceil_div(4*64*32*16 + 4*64*2048, 256), 256>>>(
        p_part, convd4_b, nullptr, p_c2, p_iw3, 4, 256, 32, 32, 128, 1048576);

    // convd3: 128->64 @64². grid (64,8,4)=2048
    packw(convd3_w, 64, 128);
    convpart_k<64,64,64,4,16><<<dim3(64, 8, 4), 64>>>(
        p_iw3, p_wpk, p_part, 128, 64, 32);
    // fused: combine + lrelu + IWT + concat with c1 -> iw2
    comb4iwtcat_k<false><<<ceil_div(4*16*64*32 + 4*16*8192, 256), 256>>>(
        p_part, convd3_b, nullptr, p_c1, p_iw2, 4, 64, 64, 64, 32, 1048576);

    // convd2: 32->16 @128². grid (256,2,4)=2048
    packw(convd2_w, 16, 32);
    convpart_k<128,128,64,4,8><<<dim3(256, 2, 4), 64>>>(
        p_iw2, p_wpk, p_part, 32, 16, 8);
    combine4_k<true,false><<<ceil_div(1048576/2, 256), 256>>>(
        p_part, convd2_b, nullptr, p_ic1, 16, 128*128, 1048576);

    // convd1: 16->12 @128². NP=3. grid (256,2,4)=2048
    packw(convd1_w, 12, 16);
    convpart_k<128,128,64,3,4><<<dim3(256, 2, 4), 64>>>(
        p_ic1, p_wpk, p_part, 16, 12, 4);
    combine4_k<true,false><<<ceil_div(786432/2, 256), 256>>>(
        p_part, convd1_b, nullptr, p_iw1, 12, 128*128, 786432);

    // fused final iwt + 1x1
    final_k<<<ceil_div(4*128*128, 256), 256>>>(p_iw1, cfin_w, out, 4);
}

// round 16
// speedup vs baseline: 1.0980x; 1.0980x over previous
#include <cuda_runtime.h>
#include <cstdint>

typedef unsigned long long ull;

// ---------------------------------------------------------------------------
// Scratch buffers (device globals; no allocation allowed)
// ---------------------------------------------------------------------------
__device__ float g_w1 [786432];    // [4,12,128,128]
__device__ float g_c1 [1048576];   // [4,16,128,128]
__device__ float g_w2 [1048576];   // [4,64,64,64]
__device__ float g_c2 [1048576];   // [4,64,64,64]
__device__ float g_w3 [1048576];   // [4,256,32,32]
__device__ float g_c3 [1048576];   // [4,256,32,32]
__device__ float g_w4 [1048576];   // [4,1024,16,16]
__device__ float g_c4 [1048576];
__device__ float g_c5 [1048576];
__device__ float g_iw4[2097152];   // [4,512,32,32]
__device__ float g_iw3[2097152];   // [4,128,64,64]
__device__ float g_iw2[2097152];   // [4,32,128,128]
__device__ float g_ic1[1048576];   // [4,16,128,128]
__device__ float g_iw1[786432];    // [4,12,128,128]
__device__ float g_part[4194304];  // 4 x 1M partial-sum buffers
__device__ float2 g_wpk[4718592];  // packed weights [IC*9][OC/2] (max: conv4)

// ---------------------------------------------------------------------------
// f32x2 packed helpers (Blackwell FFMA2)
// ---------------------------------------------------------------------------
__device__ __forceinline__ ull pk(float x, float y) {
    ull r;
    asm("mov.b64 %0, {%1, %2};" : "=l"(r) : "f"(x), "f"(y));
    return r;
}
__device__ __forceinline__ void upk(float& x, float& y, ull v) {
    asm("mov.b64 {%0, %1}, %2;" : "=f"(x), "=f"(y) : "l"(v));
}
__device__ __forceinline__ void fma2(ull& d, ull a, ull b) {
    asm("fma.rn.f32x2 %0, %1, %2, %0;" : "+l"(d) : "l"(a), "l"(b));
}

// ---------------------------------------------------------------------------
// Weight pre-pack: w[OC][IC][9] -> wpk[t9][ocpair] with t9 = ic*9+t.
// ---------------------------------------------------------------------------
__global__ void packw_k(const float* __restrict__ w, float2* __restrict__ wpk,
                        int OCp, int IC9) {
    int i = blockIdx.x * blockDim.x + threadIdx.x;
    int total = OCp * IC9;
    if (i >= total) return;
    int p  = i / IC9;
    int t9 = i - p * IC9;
    float a = w[(size_t)(2 * p) * IC9 + t9];
    float b = w[(size_t)(2 * p + 1) * IC9 + t9];
    wpk[(size_t)t9 * OCp + p] = make_float2(a, b);
}

// ---------------------------------------------------------------------------
// Haar DWT (standalone — only for the network input x)
// ---------------------------------------------------------------------------
__global__ void wt_k(const float* __restrict__ in, float* __restrict__ out,
                     int B, int C, int H, int W) {
    int Ho = H >> 1, Wo = W >> 1;
    int total = B * C * Ho * Wo;
    int i = blockIdx.x * blockDim.x + threadIdx.x;
    if (i >= total) return;
    int w = i % Wo;
    int h = (i / Wo) % Ho;
    int c = (i / (Wo * Ho)) % C;
    int b = i / (Wo * Ho * C);
    const float* p = in + ((size_t)(b * C + c) * H + 2 * h) * W + 2 * w;
    float a  = p[0], bb = p[1], cc = p[W], d = p[W + 1];
    float ll = 0.25f * (a + bb + cc + d);
    float hl = 0.5f  * (a + bb - cc - d);
    float lh = 0.5f  * (a - bb + cc - d);
    float hh = 0.5f  * (a - bb - cc + d);
    size_t ob = ((size_t)(b * 4 * C + 4 * c) * Ho + h) * Wo + w;
    size_t cs = (size_t)Ho * Wo;
    out[ob]          = ll;
    out[ob + cs]     = (hl + 1.f) * 0.5f;
    out[ob + 2 * cs] = (lh + 1.f) * 0.5f;
    out[ob + 3 * cs] = (hh + 1.f) * 0.5f;
}

// ---------------------------------------------------------------------------
// Partial direct 3x3 conv, pad=1 — oc-pair lane packing, 2x2 px per thread.
// Pre-packed weights streamed straight into smem. NP oc-pairs per thread,
// explicit per-thread input double-buffer. 64-thread blocks, 10 blocks/SM.
// ---------------------------------------------------------------------------
template <int H, int W, int TPX, int NP, int ICCHUNK>
__global__ void __launch_bounds__(TPX, 10)
convpart_k(const float* __restrict__ in, const float2* __restrict__ wpk,
           float* __restrict__ part, int IC, int OC, int ics) {
    constexpr int NT = TPX;
    constexpr int DN = ICCHUNK * 9 * NP;
    constexpr int TILESIMG = (H / 2) * (W / 2);

    __shared__ __align__(16) float2 s_pk[2][DN];

    const int tid = threadIdx.x;
    const int g   = blockIdx.x * TPX + tid;
    const int img = g / TILESIMG;
    const int rem = g % TILESIMG;
    const int h0  = (rem / (W / 2)) * 2;
    const int w0  = (rem % (W / 2)) * 2;
    const int ocp0 = blockIdx.y * NP;
    const int OCp  = OC >> 1;
    const int z   = blockIdx.z;
    const int ic0 = z * ics;

    const size_t HW = (size_t)H * W;
    const bool vr0 = (h0 > 0);
    const bool vr3 = (h0 + 2 < H);
    const bool lok = (w0 > 0);
    const bool rok = (w0 + 2 < W);

    ull acc[NP][2][2];
#pragma unroll
    for (int np = 0; np < NP; np++)
#pragma unroll
        for (int r = 0; r < 2; r++)
#pragma unroll
            for (int c = 0; c < 2; c++) acc[np][r][c] = pk(0.f, 0.f);

    const float* p0 = in + ((size_t)img * IC + ic0) * HW + (size_t)(h0 - 1) * W + (w0 - 1);
    const int nch = ics / ICCHUNK;

    auto load_chunk = [&](int c, int buf) {
        const float2* srcbase = wpk + ((size_t)(ic0 + c * ICCHUNK) * 9) * OCp + ocp0;
        if constexpr ((NP % 2) == 0) {
            for (int i = tid; i < DN / 2; i += NT) {
                int r = i / (NP / 2);
                int q = (i - r * (NP / 2)) * 2;
                const float2* src = srcbase + (size_t)r * OCp + q;
                uint32_t dst = (uint32_t)__cvta_generic_to_shared(&s_pk[buf][r * NP + q]);
                asm volatile("cp.async.ca.shared.global [%0], [%1], 16;" :: "r"(dst), "l"(src));
            }
        } else {
            for (int i = tid; i < DN; i += NT) {
                int r = i / NP;
                int q = i - r * NP;
                const float2* src = srcbase + (size_t)r * OCp + q;
                uint32_t dst = (uint32_t)__cvta_generic_to_shared(&s_pk[buf][r * NP + q]);
                asm volatile("cp.async.ca.shared.global [%0], [%1], 8;" :: "r"(dst), "l"(src));
            }
        }
    };

    load_chunk(0, 0);
    asm volatile("cp.async.commit_group;" ::: "memory");

    float cl[2][4], cx[2][4], cy[2][4], cr[2][4];

    for (int ch = 0; ch < nch; ch++) {
        asm volatile("cp.async.wait_group 0;" ::: "memory");
        __syncthreads();
        if (ch + 1 < nch) load_chunk(ch + 1, (ch + 1) & 1);
        asm volatile("cp.async.commit_group;" ::: "memory");

        const float2* wchunk = s_pk[ch & 1];
        const float* pb = p0 + (size_t)(ch * ICCHUNK) * HW;
#pragma unroll
        for (int ri = 0; ri < 4; ri++) {
            bool vr = (ri == 0) ? vr0 : (ri == 3) ? vr3 : true;
            const float* q = pb + ri * W;
            float2 m = make_float2(0.f, 0.f);
            float l = 0.f, r = 0.f;
            if (vr) {
                m = *(const float2*)(q + 1);
                if (lok) l = q[0];
                if (rok) r = q[3];
            }
            cl[0][ri] = l; cx[0][ri] = m.x; cy[0][ri] = m.y; cr[0][ri] = r;
        }

#pragma unroll 2
        for (int kk = 0; kk < ICCHUNK; kk++) {
            const int cb = kk & 1;
            if (kk + 1 < ICCHUNK) {
                const float* pn = pb + (size_t)(kk + 1) * HW;
#pragma unroll
                for (int ri = 0; ri < 4; ri++) {
                    bool vr = (ri == 0) ? vr0 : (ri == 3) ? vr3 : true;
                    const float* q = pn + ri * W;
                    float2 m = make_float2(0.f, 0.f);
                    float l = 0.f, r = 0.f;
                    if (vr) {
                        m = *(const float2*)(q + 1);
                        if (lok) l = q[0];
                        if (rok) r = q[3];
                    }
                    cl[cb ^ 1][ri] = l; cx[cb ^ 1][ri] = m.x;
                    cy[cb ^ 1][ri] = m.y; cr[cb ^ 1][ri] = r;
                }
            }
            ull bp[4][4];
#pragma unroll
            for (int ri = 0; ri < 4; ri++) {
                bp[ri][0] = pk(cl[cb][ri], cl[cb][ri]);
                bp[ri][1] = pk(cx[cb][ri], cx[cb][ri]);
                bp[ri][2] = pk(cy[cb][ri], cy[cb][ri]);
                bp[ri][3] = pk(cr[cb][ri], cr[cb][ri]);
            }
            const float2* wrow = wchunk + kk * 9 * NP;
#pragma unroll
            for (int ki = 0; ki < 3; ki++)
#pragma unroll
                for (int kj = 0; kj < 3; kj++) {
                    const int t = ki * 3 + kj;
                    ull wv[NP];
                    if constexpr ((NP % 2) == 0) {
#pragma unroll
                        for (int q2 = 0; q2 < NP / 2; q2++) {
                            ulonglong2 u = *(const ulonglong2*)&wrow[t * NP + 2 * q2];
                            wv[2 * q2]     = u.x;
                            wv[2 * q2 + 1] = u.y;
                        }
                    } else {
#pragma unroll
                        for (int np = 0; np < NP; np++)
                            wv[np] = *(const ull*)&wrow[t * NP + np];
                    }
#pragma unroll
                    for (int np = 0; np < NP; np++) {
                        fma2(acc[np][0][0], bp[ki][kj],         wv[np]);
                        fma2(acc[np][0][1], bp[ki][kj + 1],     wv[np]);
                        fma2(acc[np][1][0], bp[ki + 1][kj],     wv[np]);
                        fma2(acc[np][1][1], bp[ki + 1][kj + 1], wv[np]);
                    }
                }
        }
    }

    float* pout = part + (size_t)z * 4 * OC * HW;
#pragma unroll
    for (int np = 0; np < NP; np++) {
        float a00, b00, a01, b01, a10, b10, a11, b11;
        upk(a00, b00, acc[np][0][0]); upk(a01, b01, acc[np][0][1]);
        upk(a10, b10, acc[np][1][0]); upk(a11, b11, acc[np][1][1]);
        const int ocA = 2 * (ocp0 + np);
        size_t baseA = ((size_t)(img * OC + ocA) * H + h0) * W + w0;
        size_t baseB = baseA + HW;
        *(float2*)&pout[baseA]     = make_float2(a00, a01);
        *(float2*)&pout[baseA + W] = make_float2(a10, a11);
        *(float2*)&pout[baseB]     = make_float2(b00, b01);
        *(float2*)&pout[baseB + W] = make_float2(b10, b11);
    }
}

// ---------------------------------------------------------------------------
// Combine four partial buffers: out = act(p0+p1+p2+p3 + bias (+skip))
// ---------------------------------------------------------------------------
template <bool RELU, bool ADD>
__global__ void combine4_k(const float* __restrict__ part, const float* __restrict__ bias,
                           const float* __restrict__ addsrc, float* __restrict__ out,
                           int OC, int HW, int total) {
    int i = (blockIdx.x * blockDim.x + threadIdx.x) * 2;
    if (i >= total) return;
    int c = (i / HW) % OC;
    float2 p0 = *(const float2*)&part[i];
    float2 p1 = *(const float2*)&part[total + i];
    float2 p2 = *(const float2*)&part[2 * (size_t)total + i];
    float2 p3 = *(const float2*)&part[3 * (size_t)total + i];
    float bv = bias[c];
    float v0 = (p0.x + p1.x) + (p2.x + p3.x) + bv;
    float v1 = (p0.y + p1.y) + (p2.y + p3.y) + bv;
    if (ADD) {
        float2 s = *(const float2*)&addsrc[i];
        v0 += s.x; v1 += s.y;
    }
    if (RELU) {
        v0 = (v0 >= 0.f) ? v0 : 0.2f * v0;
        v1 = (v1 >= 0.f) ? v1 : 0.2f * v1;
    }
    *(float2*)&out[i] = make_float2(v0, v1);
}

// ---------------------------------------------------------------------------
// Combine four partials + lrelu + fused Haar DWT of the result.
// ---------------------------------------------------------------------------
__global__ void combine4wt_k(const float* __restrict__ part, const float* __restrict__ bias,
                             float* __restrict__ out, float* __restrict__ wtout,
                             int OC, int H, int W, int total) {
    int HW = H * W;
    int nblk = total / 4;
    int i = blockIdx.x * blockDim.x + threadIdx.x;
    if (i >= nblk) return;
    int Wh = W / 2;
    int w2 = i % Wh;
    int h2 = (i / Wh) % (H / 2);
    int bc = i / (HW / 4);
    size_t base = (size_t)bc * HW + (size_t)(2 * h2) * W + 2 * w2;
    float bv = bias[bc % OC];
    float v00 = bv, v01 = bv, v10 = bv, v11 = bv;
#pragma unroll
    for (int z = 0; z < 4; z++) {
        const float* p = part + (size_t)z * total;
        float2 a = *(const float2*)&p[base];
        float2 b = *(const float2*)&p[base + W];
        v00 += a.x; v01 += a.y; v10 += b.x; v11 += b.y;
    }
    v00 = (v00 >= 0.f) ? v00 : 0.2f * v00;
    v01 = (v01 >= 0.f) ? v01 : 0.2f * v01;
    v10 = (v10 >= 0.f) ? v10 : 0.2f * v10;
    v11 = (v11 >= 0.f) ? v11 : 0.2f * v11;
    *(float2*)&out[base]     = make_float2(v00, v01);
    *(float2*)&out[base + W] = make_float2(v10, v11);

    float ll = 0.25f * (v00 + v01 + v10 + v11);
    float hl = 0.5f  * (v00 + v01 - v10 - v11);
    float lh = 0.5f  * (v00 - v01 + v10 - v11);
    float hh = 0.5f  * (v00 - v01 - v10 + v11);
    hl = (hl + 1.f) * 0.5f; lh = (lh + 1.f) * 0.5f; hh = (hh + 1.f) * 0.5f;
    int c = bc % OC, b_ = bc / OC;
    size_t cs = (size_t)HW / 4;
    size_t ob = ((size_t)(b_ * 4 * OC + 4 * c)) * cs + (size_t)h2 * Wh + w2;
    wtout[ob]          = ll;
    wtout[ob + cs]     = hl;
    wtout[ob + 2 * cs] = lh;
    wtout[ob + 3 * cs] = hh;
}

// ---------------------------------------------------------------------------
// Fused: combine four partials (+ optional skip-add) + lrelu + IWT + concat.
// ---------------------------------------------------------------------------
template <bool ADD>
__global__ void comb4iwtcat_k(const float* __restrict__ part, const float* __restrict__ bias,
                              const float* __restrict__ addsrc, const float* __restrict__ skip,
                              float* __restrict__ out,
                              int B, int C4, int H, int W, int Ctot, int total) {
    int C = C4 >> 2;
    int Csrc = Ctot - C;
    int Wh = W / 2;
    int Niwt = B * C * H * Wh;
    int HWo = 4 * H * W;
    int npc = HWo / 2;
    int Ncopy2 = B * Csrc * npc;
    int i = blockIdx.x * blockDim.x + threadIdx.x;
    if (i < Niwt) {
        int w0 = (i % Wh) * 2;
        int h  = (i / Wh) % H;
        int c  = (i / (Wh * H)) % C;
        int b  = i / (Wh * H * C);
        float2 v[4];
#pragma unroll
        for (int k = 0; k < 4; k++) {
            size_t base = ((size_t)(b * C4 + 4 * c + k) * H + h) * W + w0;
            float2 s0 = *(const float2*)&part[base];
            float2 s1 = *(const float2*)&part[(size_t)total + base];
            float2 s2 = *(const float2*)&part[2 * (size_t)total + base];
            float2 s3 = *(const float2*)&part[3 * (size_t)total + base];
            float bv = bias[4 * c + k];
            float x = (s0.x + s1.x) + (s2.x + s3.x) + bv;
            float y = (s0.y + s1.y) + (s2.y + s3.y) + bv;
            if (ADD) {
                float2 a = *(const float2*)&addsrc[base];
                x += a.x; y += a.y;
            }
            x = (x >= 0.f) ? x : 0.2f * x;
            y = (y >= 0.f) ? y : 0.2f * y;
            if (k) { x = 2.f * x - 1.f; y = 2.f * y - 1.f; }
            v[k] = make_float2(x, y);
        }
        float x00a = v[0].x + 0.5f * ( v[1].x + v[2].x + v[3].x);
        float x01a = v[0].x + 0.5f * ( v[1].x - v[2].x - v[3].x);
        float x10a = v[0].x + 0.5f * (-v[1].x + v[2].x - v[3].x);
        float x11a = v[0].x + 0.5f * (-v[1].x - v[2].x + v[3].x);
        float x00b = v[0].y + 0.5f * ( v[1].y + v[2].y + v[3].y);
        float x01b = v[0].y + 0.5f * ( v[1].y - v[2].y - v[3].y);
        float x10b = v[0].y + 0.5f * (-v[1].y + v[2].y - v[3].y);
        float x11b = v[0].y + 0.5f * (-v[1].y - v[2].y + v[3].y);
        int W2 = 2 * W;
        size_t ob = ((size_t)(b * Ctot + Csrc + c) * 2 * H + 2 * h) * W2 + 2 * w0;
        *(float4*)&out[ob]      = make_float4(x00a, x01a, x00b, x01b);
        *(float4*)&out[ob + W2] = make_float4(x10a, x11a, x10b, x11b);
    } else {
        int j = i - Niwt;
        if (j >= Ncopy2) return;
        int pos = j % npc;
        int c   = (j / npc) % Csrc;
        int b   = j / (npc * Csrc);
        *(float2*)&out[((size_t)(b * Ctot) + c) * HWo + 2 * pos] =
            *(const float2*)&skip[((size_t)(b * Csrc) + c) * HWo + 2 * pos];
    }
}

// ---------------------------------------------------------------------------
// Final: y = iwt(iw1[4,12,128,128]); out = 1x1 conv cfin @ y -> [4,3,256,256]
// ---------------------------------------------------------------------------
__global__ void final_k(const float* __restrict__ in, const float* __restrict__ cfin,
                        float* __restrict__ out, int B) {
    const int H = 128, W = 128;
    int total = B * H * W;
    int i = blockIdx.x * blockDim.x + threadIdx.x;
    if (i >= total) return;
    int w = i % W;
    int h = (i / W) % H;
    int b = i / (W * H);

    float y00[3], y01[3], y10[3], y11[3];
#pragma unroll
    for (int c = 0; c < 3; c++) {
        size_t ib = ((size_t)(b * 12 + 4 * c) * H + h) * W + w;
        size_t cs = (size_t)H * W;
        float v0 = in[ib];
        float v1 = 2.f * in[ib + cs]     - 1.f;
        float v2 = 2.f * in[ib + 2 * cs] - 1.f;
        float v3 = 2.f * in[ib + 3 * cs] - 1.f;
        y00[c] = v0 + 0.5f * ( v1 + v2 + v3);
        y01[c] = v0 + 0.5f * ( v1 - v2 - v3);
        y10[c] = v0 + 0.5f * (-v1 + v2 - v3);
        y11[c] = v0 + 0.5f * (-v1 - v2 + v3);
    }
    float m[9];
#pragma unroll
    for (int j = 0; j < 9; j++) m[j] = cfin[j];

    const int HO = 256, WO = 256;
#pragma unroll
    for (int o = 0; o < 3; o++) {
        float o00 = m[o*3+0]*y00[0] + m[o*3+1]*y00[1] + m[o*3+2]*y00[2];
        float o01 = m[o*3+0]*y01[0] + m[o*3+1]*y01[1] + m[o*3+2]*y01[2];
        float o10 = m[o*3+0]*y10[0] + m[o*3+1]*y10[1] + m[o*3+2]*y10[2];
        float o11 = m[o*3+0]*y11[0] + m[o*3+1]*y11[1] + m[o*3+2]*y11[2];
        size_t ob = ((size_t)(b * 3 + o) * HO + 2 * h) * WO + 2 * w;
        out[ob]          = o00;
        out[ob + 1]      = o01;
        out[ob + WO]     = o10;
        out[ob + WO + 1] = o11;
    }
}

// ---------------------------------------------------------------------------
// Host side
// ---------------------------------------------------------------------------
static inline int ceil_div(int a, int b) { return (a + b - 1) / b; }

extern "C" void kernel_launch(void* const* d_in, const int* in_sizes, int n_in,
                              void* d_out, int out_size) {
    (void)in_sizes; (void)n_in; (void)out_size;
    const float* x        = (const float*)d_in[0];
    const float* conv1_w  = (const float*)d_in[1];
    const float* conv1_b  = (const float*)d_in[2];
    const float* conv2_w  = (const float*)d_in[3];
    const float* conv2_b  = (const float*)d_in[4];
    const float* conv3_w  = (const float*)d_in[5];
    const float* conv3_b  = (const float*)d_in[6];
    const float* conv4_w  = (const float*)d_in[7];
    const float* conv4_b  = (const float*)d_in[8];
    const float* convd4_w = (const float*)d_in[9];
    const float* convd4_b = (const float*)d_in[10];
    const float* convd3_w = (const float*)d_in[11];
    const float* convd3_b = (const float*)d_in[12];
    const float* convd2_w = (const float*)d_in[13];
    const float* convd2_b = (const float*)d_in[14];
    const float* convd1_w = (const float*)d_in[15];
    const float* convd1_b = (const float*)d_in[16];
    const float* cfin_w   = (const float*)d_in[17];
    float* out = (float*)d_out;

    static float *p_w1=nullptr,*p_c1,*p_w2,*p_c2,*p_w3,*p_c3,*p_w4,*p_c4,*p_c5,
                 *p_iw4,*p_iw3,*p_iw2,*p_ic1,*p_iw1,*p_part;
    static float2 *p_wpk;
    if (!p_w1) {
        cudaGetSymbolAddress((void**)&p_w1,  g_w1);
        cudaGetSymbolAddress((void**)&p_c1,  g_c1);
        cudaGetSymbolAddress((void**)&p_w2,  g_w2);
        cudaGetSymbolAddress((void**)&p_c2,  g_c2);
        cudaGetSymbolAddress((void**)&p_w3,  g_w3);
        cudaGetSymbolAddress((void**)&p_c3,  g_c3);
        cudaGetSymbolAddress((void**)&p_w4,  g_w4);
        cudaGetSymbolAddress((void**)&p_c4,  g_c4);
        cudaGetSymbolAddress((void**)&p_c5,  g_c5);
        cudaGetSymbolAddress((void**)&p_iw4, g_iw4);
        cudaGetSymbolAddress((void**)&p_iw3, g_iw3);
        cudaGetSymbolAddress((void**)&p_iw2, g_iw2);
        cudaGetSymbolAddress((void**)&p_ic1, g_ic1);
        cudaGetSymbolAddress((void**)&p_iw1, g_iw1);
        cudaGetSymbolAddress((void**)&p_part, g_part);
        cudaGetSymbolAddress((void**)&p_wpk, g_wpk);
    }

    auto packw = [&](const float* w, int OC, int IC) {
        int OCp = OC / 2, IC9 = IC * 9;
        packw_k<<<ceil_div(OCp * IC9, 256), 256>>>(w, p_wpk, OCp, IC9);
    };

    // w1 = wt(x)
    wt_k<<<ceil_div(4*3*128*128, 256), 256>>>(x, p_w1, 4, 3, 256, 256);

    // conv1: 12->16 @128². grid (256,2,4)=2048 x64
    packw(conv1_w, 16, 12);
    convpart_k<128,128,64,4,3><<<dim3(256, 2, 4), 64>>>(
        p_w1, p_wpk, p_part, 12, 16, 3);
    combine4wt_k<<<ceil_div(1048576/4, 256), 256>>>(
        p_part, conv1_b, p_c1, p_w2, 16, 128, 128, 1048576);

    // conv2: 64->64 @64². grid (64,8,4)=2048
    packw(conv2_w, 64, 64);
    convpart_k<64,64,64,4,16><<<dim3(64, 8, 4), 64>>>(
        p_w2, p_wpk, p_part, 64, 64, 16);
    combine4wt_k<<<ceil_div(1048576/4, 256), 256>>>(
        p_part, conv2_b, p_c2, p_w3, 64, 64, 64, 1048576);

    // conv3: 256->256 @32². grid (16,32,4)=2048
    packw(conv3_w, 256, 256);
    convpart_k<32,32,64,4,16><<<dim3(16, 32, 4), 64>>>(
        p_w3, p_wpk, p_part, 256, 256, 64);
    combine4wt_k<<<ceil_div(1048576/4, 256), 256>>>(
        p_part, conv3_b, p_c3, p_w4, 256, 32, 32, 1048576);

    // bottleneck: three conv4 1024->1024 @16². grid (4,128,4)=2048
    packw(conv4_w, 1024, 1024);
    convpart_k<16,16,64,4,16><<<dim3(4, 128, 4), 64>>>(
        p_w4, p_wpk, p_part, 1024, 1024, 256);
    combine4_k<true,false><<<ceil_div(1048576/2, 256), 256>>>(
        p_part, conv4_b, nullptr, p_c4, 1024, 16*16, 1048576);
    convpart_k<16,16,64,4,16><<<dim3(4, 128, 4), 64>>>(
        p_c4, p_wpk, p_part, 1024, 1024, 256);
    combine4_k<true,false><<<ceil_div(1048576/2, 256), 256>>>(
        p_part, conv4_b, nullptr, p_c5, 1024, 16*16, 1048576);
    convpart_k<16,16,64,4,16><<<dim3(4, 128, 4), 64>>>(
        p_c5, p_wpk, p_part, 1024, 1024, 256);
    // fused: combine + w4 skip-add + lrelu + IWT + concat with c3 -> iw4
    comb4iwtcat_k<true><<<ceil_div(4*256*16*8 + 4*256*512, 256), 256>>>(
        p_part, conv4_b, p_w4, p_c3, p_iw4, 4, 1024, 16, 16, 512, 1048576);

    // convd4: 512->256 @32². grid (16,32,4)=2048
    packw(convd4_w, 256, 512);
    convpart_k<32,32,64,4,16><<<dim3(16, 32, 4), 64>>>(
        p_iw4, p_wpk, p_part, 512, 256, 128);
    // fused: combine + lrelu + IWT + concat with c2 -> iw3
    comb4iwtcat_k<false><<<ceil_div(4*64*32*16 + 4*64*2048, 256), 256>>>(
        p_part, convd4_b, nullptr, p_c2, p_iw3, 4, 256, 32, 32, 128, 1048576);

    // convd3: 128->64 @64². grid (64,8,4)=2048
    packw(convd3_w, 64, 128);
    convpart_k<64,64,64,4,16><<<dim3(64, 8, 4), 64>>>(
        p_iw3, p_wpk, p_part, 128, 64, 32);
    // fused: combine + lrelu + IWT + concat with c1 -> iw2
    comb4iwtcat_k<false><<<ceil_div(4*16*64*32 + 4*16*8192, 256), 256>>>(
        p_part, convd3_b, nullptr, p_c1, p_iw2, 4, 64, 64, 64, 32, 1048576);

    // convd2: 32->16 @128². grid (256,2,4)=2048
    packw(convd2_w, 16, 32);
    convpart_k<128,128,64,4,8><<<dim3(256, 2, 4), 64>>>(
        p_iw2, p_wpk, p_part, 32, 16, 8);
    combine4_k<true,false><<<ceil_div(1048576/2, 256), 256>>>(
        p_part, convd2_b, nullptr, p_ic1, 16, 128*128, 1048576);

    // convd1: 16->12 @128². NP=3. grid (256,2,4)=2048
    packw(convd1_w, 12, 16);
    convpart_k<128,128,64,3,4><<<dim3(256, 2, 4), 64>>>(
        p_ic1, p_wpk, p_part, 16, 12, 4);
    combine4_k<true,false><<<ceil_div(786432/2, 256), 256>>>(
        p_part, convd1_b, nullptr, p_iw1, 12, 128*128, 786432);

    // fused final iwt + 1x1
    final_k<<<ceil_div(4*128*128, 256), 256>>>(p_iw1, cfin_w, out, 4);
}